// round 4
// baseline (speedup 1.0000x reference)
#include <cuda_runtime.h>

#define NN 50000
#define EE 800000
#define GG 64

// ---------------- scratch (device globals; no allocation allowed) ----------------
__device__ float g_h[NN * 128];
__device__ float g_agg[NN * 128];
__device__ float g_x[NN * 64];
__device__ float g_s[NN * 64];
__device__ float g_tmp[NN * 64];
__device__ float g_snew[NN * 64];
__device__ float g_out[NN * 64];
__device__ int   g_deg[NN];
__device__ float g_dinv[NN];
__device__ float g_colsum[128];   // [0:64) sum, [64:128) sumsq
__device__ float g_bnp[128];      // [0:64) mean, [64:128) rstd

__device__ __forceinline__ void red_add_v4(float* addr, float4 v) {
    asm volatile("red.global.add.v4.f32 [%0], {%1, %2, %3, %4};"
                 :: "l"(addr), "f"(v.x), "f"(v.y), "f"(v.z), "f"(v.w)
                 : "memory");
}

// ---------------- setup ----------------
__global__ void k_init(const float4* __restrict__ x, const float4* __restrict__ s) {
    int i = blockIdx.x * blockDim.x + threadIdx.x;
    if (i < NN * 16) {
        ((float4*)g_x)[i] = x[i];
        ((float4*)g_s)[i] = s[i];
    }
    if (i < NN) g_deg[i] = 0;
}

__global__ void k_deg(const int* __restrict__ dst) {
    int e = blockIdx.x * blockDim.x + threadIdx.x;
    if (e < EE) {
        int d = dst[e];
        if (d >= 0 && d < NN) atomicAdd(&g_deg[d], 1);
    }
}

__global__ void k_dinv() {
    int i = blockIdx.x * blockDim.x + threadIdx.x;
    if (i < NN) g_dinv[i] = rsqrtf((float)g_deg[i] + 1.0f);  // +1 self loop, always > 0
}

// ---------------- GIN ----------------
__global__ void k_build_h(int zero_bn) {
    int i = blockIdx.x * blockDim.x + threadIdx.x;
    if (i < NN * 32) {
        int n = i >> 5, l = i & 31;
        float4 v = (l < 16) ? ((const float4*)g_x)[n * 16 + l]
                            : ((const float4*)g_s)[n * 16 + (l - 16)];
        ((float4*)g_h)[i]   = v;
        ((float4*)g_agg)[i] = v;
    }
    if (zero_bn && blockIdx.x == 0 && threadIdx.x < 128) g_colsum[threadIdx.x] = 0.f;
}

// warp per edge: 32 lanes x float4 = 512B row
__global__ void k_gin_scatter(const int* __restrict__ src,
                              const int* __restrict__ dst) {
    int i = blockIdx.x * blockDim.x + threadIdx.x;
    if (i >= EE * 32) return;
    int e = i >> 5, l = i & 31;
    int sv = src[e], dv = dst[e];
    float4 v = ((const float4*)g_h)[sv * 32 + l];
    red_add_v4(&g_agg[dv * 128 + l * 4], v);
}

// ---------------- GEMM: out[N,64] = act(A[N,K] @ W[K,64]) ----------------
template <int K, bool LEAKY, bool BNACC>
__global__ __launch_bounds__(256) void k_gemm(const float* __restrict__ A,
                                              const float* __restrict__ W,
                                              float* __restrict__ out) {
    __shared__ float Ws[K * 64];
    __shared__ float As[16 * K];
    int tid = threadIdx.x;
    for (int i = tid; i < K * 16; i += 256)
        ((float4*)Ws)[i] = ((const float4*)W)[i];
    int c = tid & 63, tg = tid >> 6;
    float bsum = 0.f, bsq = 0.f;
    for (int tile = blockIdx.x; tile < NN / 16; tile += gridDim.x) {
        __syncthreads();
        const float4* Ag = (const float4*)(A + tile * 16 * K);
        for (int i = tid; i < 4 * K; i += 256)
            ((float4*)As)[i] = Ag[i];
        __syncthreads();
        float acc0 = 0.f, acc1 = 0.f, acc2 = 0.f, acc3 = 0.f;
        const float* a0 = &As[(tg * 4 + 0) * K];
        const float* a1 = &As[(tg * 4 + 1) * K];
        const float* a2 = &As[(tg * 4 + 2) * K];
        const float* a3 = &As[(tg * 4 + 3) * K];
#pragma unroll
        for (int k = 0; k < K; k += 4) {
            float w0 = Ws[(k + 0) * 64 + c], w1 = Ws[(k + 1) * 64 + c];
            float w2 = Ws[(k + 2) * 64 + c], w3 = Ws[(k + 3) * 64 + c];
            float4 v;
            v = *(const float4*)(a0 + k); acc0 += v.x * w0 + v.y * w1 + v.z * w2 + v.w * w3;
            v = *(const float4*)(a1 + k); acc1 += v.x * w0 + v.y * w1 + v.z * w2 + v.w * w3;
            v = *(const float4*)(a2 + k); acc2 += v.x * w0 + v.y * w1 + v.z * w2 + v.w * w3;
            v = *(const float4*)(a3 + k); acc3 += v.x * w0 + v.y * w1 + v.z * w2 + v.w * w3;
        }
        int row0 = tile * 16 + tg * 4;
        float r[4] = {acc0, acc1, acc2, acc3};
#pragma unroll
        for (int j = 0; j < 4; j++) {
            float v = r[j];
            if (LEAKY) v = v > 0.f ? v : 0.01f * v;
            out[(row0 + j) * 64 + c] = v;
            if (BNACC) { bsum += v; bsq += v * v; }
        }
    }
    if (BNACC) {
        __syncthreads();
        As[tg * 64 + c] = bsum;
        As[256 + tg * 64 + c] = bsq;
        __syncthreads();
        if (tg == 0) {
            float s0 = As[c] + As[64 + c] + As[128 + c] + As[192 + c];
            float q0 = As[256 + c] + As[320 + c] + As[384 + c] + As[448 + c];
            atomicAdd(&g_colsum[c], s0);
            atomicAdd(&g_colsum[64 + c], q0);
        }
    }
}

// ---------------- BatchNorm (only the last layer's BN output is used) ----------------
__global__ void k_bn_fin() {
    int c = threadIdx.x;  // 64 threads
    float m   = g_colsum[c] * (1.0f / NN);
    float var = g_colsum[64 + c] * (1.0f / NN) - m * m;
    g_bnp[c]      = m;
    g_bnp[64 + c] = rsqrtf(var + 1e-4f);
}

__global__ void k_bn_apply(const float* __restrict__ gamma, const float* __restrict__ beta,
                           float* __restrict__ xl, long long limit) {
    int i = blockIdx.x * blockDim.x + threadIdx.x;
    if (i < NN * 64) {
        int c = i & 63;
        float v = gamma[c] * (g_x[i] - g_bnp[c]) * g_bnp[64 + c] + beta[c];
        if ((long long)i < limit) xl[i] = v;
    }
}

// ---------------- GCN ----------------
__global__ void k_gcn_init() {   // self loop: dinv[n]^2 * sw[n]
    int i = blockIdx.x * blockDim.x + threadIdx.x;
    if (i < NN * 16) {
        int n = i >> 4;
        float d = g_dinv[n];
        float coef = d * d;
        float4 v = ((const float4*)g_tmp)[i];
        v.x *= coef; v.y *= coef; v.z *= coef; v.w *= coef;
        ((float4*)g_snew)[i] = v;
    }
}

__global__ void k_gcn_scatter(const int* __restrict__ src,
                              const int* __restrict__ dst) {
    int i = blockIdx.x * blockDim.x + threadIdx.x;
    if (i >= EE * 16) return;
    int e = i >> 4, l = i & 15;
    int sv = src[e], dv = dst[e];
    float coef = g_dinv[sv] * g_dinv[dv];
    float4 v = ((const float4*)g_tmp)[sv * 16 + l];
    v.x *= coef; v.y *= coef; v.z *= coef; v.w *= coef;
    red_add_v4(&g_snew[dv * 64 + l * 4], v);
}

__global__ void k_gcn_fin(const float* __restrict__ bg) {
    int i = blockIdx.x * blockDim.x + threadIdx.x;
    if (i < NN * 64) {
        int c = i & 63;
        g_s[i] = tanhf(g_snew[i] + bg[c]);
    }
}

// ---------------- final: g_out = concat(x_local, s) @ Wh + bh ----------------
__global__ __launch_bounds__(256) void k_final_gemm(const float* __restrict__ xl,
                                                    const float* __restrict__ W,
                                                    const float* __restrict__ bias) {
    __shared__ float Ws[128 * 64];
    __shared__ float As[16 * 128];
    int tid = threadIdx.x;
    for (int i = tid; i < 128 * 16; i += 256)
        ((float4*)Ws)[i] = ((const float4*)W)[i];
    int c = tid & 63, tg = tid >> 6;
    float bval = bias[c];
    for (int tile = blockIdx.x; tile < NN / 16; tile += gridDim.x) {
        __syncthreads();
        for (int i = tid; i < 512; i += 256) {
            int r = i >> 5, kk = i & 31;
            int row = tile * 16 + r;
            float4 v = (kk < 16) ? ((const float4*)xl)[row * 16 + kk]
                                 : ((const float4*)g_s)[row * 16 + (kk - 16)];
            ((float4*)As)[i] = v;
        }
        __syncthreads();
        float acc0 = bval, acc1 = bval, acc2 = bval, acc3 = bval;
        const float* a0 = &As[(tg * 4 + 0) * 128];
        const float* a1 = &As[(tg * 4 + 1) * 128];
        const float* a2 = &As[(tg * 4 + 2) * 128];
        const float* a3 = &As[(tg * 4 + 3) * 128];
#pragma unroll
        for (int k = 0; k < 128; k += 4) {
            float w0 = Ws[(k + 0) * 64 + c], w1 = Ws[(k + 1) * 64 + c];
            float w2 = Ws[(k + 2) * 64 + c], w3 = Ws[(k + 3) * 64 + c];
            float4 v;
            v = *(const float4*)(a0 + k); acc0 += v.x * w0 + v.y * w1 + v.z * w2 + v.w * w3;
            v = *(const float4*)(a1 + k); acc1 += v.x * w0 + v.y * w1 + v.z * w2 + v.w * w3;
            v = *(const float4*)(a2 + k); acc2 += v.x * w0 + v.y * w1 + v.z * w2 + v.w * w3;
            v = *(const float4*)(a3 + k); acc3 += v.x * w0 + v.y * w1 + v.z * w2 + v.w * w3;
        }
        int row0 = tile * 16 + tg * 4;
        g_out[(row0 + 0) * 64 + c] = acc0;
        g_out[(row0 + 1) * 64 + c] = acc1;
        g_out[(row0 + 2) * 64 + c] = acc2;
        g_out[(row0 + 3) * 64 + c] = acc3;
    }
}

// ---------------- pool: batch is SORTED -> binary-search range sum ----------------
__device__ __forceinline__ int lower_bound_i(const int* a, int key) {
    int lo = 0, hi = NN;
    while (lo < hi) {
        int mid = (lo + hi) >> 1;
        if (a[mid] < key) lo = mid + 1; else hi = mid;
    }
    return lo;
}

__global__ void k_pool(const int* __restrict__ batch, float* __restrict__ pooled,
                       long long limit) {
    int g = blockIdx.x;
    int tid = threadIdx.x;
    int c = tid & 63, p = tid >> 6;  // 4 partial sums per column
    int lo = lower_bound_i(batch, g);
    int hi = lower_bound_i(batch, g + 1);
    float acc = 0.f;
    for (int r = lo + p; r < hi; r += 4) acc += g_out[r * 64 + c];
    __shared__ float red[256];
    red[tid] = acc;
    __syncthreads();
    if (p == 0) {
        long long oi = (long long)g * 64 + c;
        if (oi < limit)
            pooled[oi] = red[c] + red[64 + c] + red[128 + c] + red[192 + c];
    }
}

// ---------------- launch ----------------
extern "C" void kernel_launch(void* const* d_in, const int* in_sizes, int n_in,
                              void* d_out, int out_size) {
    // Identify inputs by element count (robust to metadata ordering).
    // Sizes: x/s = 3,200,000 ; W1 = 24,576 ; W2/Wg = 12,288 ; gamma/beta/bg = 192 ;
    //        Wh = 8,192 ; bh = 64 ; edge_index = 1,600,000 ; batch = 50,000.
    const float *x = 0, *s = 0, *W1 = 0, *W2 = 0, *gamma = 0, *beta = 0;
    const float *Wg = 0, *bg = 0, *Wh = 0, *bh = 0;
    const int *ei = 0, *batch = 0;
    for (int i = 0; i < n_in; i++) {
        int sz = in_sizes[i];
        const void* p = d_in[i];
        switch (sz) {
            case 3200000: if (!x) x = (const float*)p; else s = (const float*)p; break;
            case 24576:   W1 = (const float*)p; break;
            case 12288:   if (!W2) W2 = (const float*)p; else Wg = (const float*)p; break;
            case 192:     if (!gamma) gamma = (const float*)p;
                          else if (!beta) beta = (const float*)p;
                          else bg = (const float*)p; break;
            case 8192:    Wh = (const float*)p; break;
            case 64:      bh = (const float*)p; break;
            case 1600000: ei = (const int*)p; break;
            case 50000:   batch = (const int*)p; break;
            default: break;
        }
    }

    const int* esrc = ei;
    const int* edst = ei + EE;

    float *p_agg, *p_tmp, *p_x, *p_s, *p_h;
    cudaGetSymbolAddress((void**)&p_agg, g_agg);
    cudaGetSymbolAddress((void**)&p_tmp, g_tmp);
    cudaGetSymbolAddress((void**)&p_x,   g_x);
    cudaGetSymbolAddress((void**)&p_s,   g_s);
    cudaGetSymbolAddress((void**)&p_h,   g_h);

    long long osz = (long long)out_size;
    float* out = (float*)d_out;
    bool full = (osz >= (long long)GG * 64 + (long long)NN * 64);
    float* xl = full ? out + GG * 64 : p_h;   // g_h is dead after the layer loop
    long long xl_lim = (long long)NN * 64;

    k_init<<<(NN * 16 + 255) / 256, 256>>>((const float4*)x, (const float4*)s);
    k_deg<<<(EE + 255) / 256, 256>>>(edst);
    k_dinv<<<(NN + 255) / 256, 256>>>();

    for (int i = 0; i < 3; i++) {
        k_build_h<<<NN * 32 / 256, 256>>>(i == 2 ? 1 : 0);
        k_gin_scatter<<<EE * 32 / 256, 256>>>(esrc, edst);
        k_gemm<128, true, false><<<592, 256>>>(p_agg, W1 + i * 128 * 64, p_tmp);
        if (i == 2)
            k_gemm<64, false, true><<<1184, 256>>>(p_tmp, W2 + i * 64 * 64, p_x);
        else
            k_gemm<64, false, false><<<1184, 256>>>(p_tmp, W2 + i * 64 * 64, p_x);
        // GCN: sw = s @ Wg[i] -> g_tmp (reused)
        k_gemm<64, false, false><<<1184, 256>>>(p_s, Wg + i * 64 * 64, p_tmp);
        k_gcn_init<<<NN * 16 / 256, 256>>>();
        k_gcn_scatter<<<EE * 16 / 256, 256>>>(esrc, edst);
        k_gcn_fin<<<NN * 64 / 256, 256>>>(bg + i * 64);
    }

    k_bn_fin<<<1, 64>>>();
    k_bn_apply<<<NN * 64 / 256, 256>>>(gamma + 2 * 64, beta + 2 * 64, xl, xl_lim);
    k_final_gemm<<<592, 256>>>(xl, Wh, bh);
    k_pool<<<GG, 256>>>(batch, out, osz);
}

// round 5
// speedup vs baseline: 1.4891x; 1.4891x over previous
#include <cuda_runtime.h>

#define NN 50000
#define EE 800000
#define GG 64

// ---------------- scratch (device globals; no allocation allowed) ----------------
__device__ float g_agg[NN * 128];
__device__ float g_x[NN * 64];
__device__ float g_s[NN * 64];
__device__ float g_tmp[NN * 64];
__device__ float g_out[NN * 64];
__device__ int   g_deg[NN];
__device__ int   g_rowstart[NN + 1];
__device__ int   g_cursor[NN];
__device__ int   g_eidx[EE];      // CSR: src indices grouped by dst
__device__ float g_dinv[NN];
__device__ float g_colsum[128];   // [0:64) sum, [64:128) sumsq
__device__ float g_bnp[128];      // [0:64) mean, [64:128) rstd

// ---------------- CSR build ----------------
__global__ void k_zero_deg() {
    int i = blockIdx.x * blockDim.x + threadIdx.x;
    if (i < NN) g_deg[i] = 0;
}

__global__ void k_deg(const int* __restrict__ dst) {
    int e = blockIdx.x * blockDim.x + threadIdx.x;
    if (e < EE) {
        int d = dst[e];
        if (d >= 0 && d < NN) atomicAdd(&g_deg[d], 1);
    }
}

__global__ void k_dinv() {
    int i = blockIdx.x * blockDim.x + threadIdx.x;
    if (i < NN) g_dinv[i] = rsqrtf((float)g_deg[i] + 1.0f);  // +1 self loop
    if (blockIdx.x == 0 && threadIdx.x < 128) g_colsum[threadIdx.x] = 0.f;
}

// single-block inclusive scan over g_deg -> g_rowstart (exclusive), cursor=rowstart
__global__ void k_scan() {
    __shared__ int sh[1024];
    __shared__ int carry_s;
    int tid = threadIdx.x;
    if (tid == 0) carry_s = 0;
    __syncthreads();
    for (int base = 0; base < NN; base += 1024) {
        int i = base + tid;
        int v = (i < NN) ? g_deg[i] : 0;
        sh[tid] = v;
        __syncthreads();
        for (int off = 1; off < 1024; off <<= 1) {
            int t = (tid >= off) ? sh[tid - off] : 0;
            __syncthreads();
            sh[tid] += t;
            __syncthreads();
        }
        int carry = carry_s;
        if (i < NN) {
            int incl = carry + sh[tid];
            g_rowstart[i + 1] = incl;
            g_cursor[i] = incl - v;  // exclusive = start of row i
        }
        __syncthreads();
        if (tid == 1023) carry_s = carry + sh[1023];
        __syncthreads();
    }
    if (tid == 0) g_rowstart[0] = 0;
}

__global__ void k_fill(const int* __restrict__ src, const int* __restrict__ dst) {
    int e = blockIdx.x * blockDim.x + threadIdx.x;
    if (e < EE) {
        int d = dst[e];
        if (d >= 0 && d < NN) {
            int pos = atomicAdd(&g_cursor[d], 1);
            g_eidx[pos] = src[e];
        }
    }
}

// ---------------- GIN gather: agg[n] = concat(x,s)[n] + sum_{src in N(n)} concat(x,s)[src]
// warp per node; lane l owns float4 l of the 128-wide row (lanes 0-15: x, 16-31: s)
__global__ __launch_bounds__(256) void k_gin_gather(const float4* __restrict__ x4,
                                                    const float4* __restrict__ s4) {
    int w = (blockIdx.x * blockDim.x + threadIdx.x) >> 5;
    if (w >= NN) return;
    int l = threadIdx.x & 31;
    int li = (l < 16) ? l : (l - 16);
    const float4* base = (l < 16) ? x4 : s4;
    float4 acc = base[w * 16 + li];
    int j = g_rowstart[w], end = g_rowstart[w + 1];
    for (; j < end; j++) {
        int sv = g_eidx[j];
        float4 v = base[sv * 16 + li];
        acc.x += v.x; acc.y += v.y; acc.z += v.z; acc.w += v.w;
    }
    ((float4*)g_agg)[w * 32 + l] = acc;
}

// ---------------- GCN gather: s = tanh( dinv[n]*(sum dinv[src]*sw[src]) + dinv[n]^2*sw[n] + bg )
// warp per node; lane l owns float2 l of the 64-wide row
__global__ __launch_bounds__(256) void k_gcn_gather(const float2* __restrict__ sw2,
                                                    const float* __restrict__ bg) {
    int w = (blockIdx.x * blockDim.x + threadIdx.x) >> 5;
    if (w >= NN) return;
    int l = threadIdx.x & 31;
    float dn = g_dinv[w];
    float2 self = sw2[w * 32 + l];
    float2 acc;
    acc.x = dn * self.x;   // will multiply by dn once more at the end
    acc.y = dn * self.y;
    int j = g_rowstart[w], end = g_rowstart[w + 1];
    for (; j < end; j++) {
        int sv = g_eidx[j];
        float ds = g_dinv[sv];
        float2 v = sw2[sv * 32 + l];
        acc.x += ds * v.x;
        acc.y += ds * v.y;
    }
    float b0 = bg[l * 2], b1 = bg[l * 2 + 1];
    float2 r;
    r.x = tanhf(dn * acc.x + b0);
    r.y = tanhf(dn * acc.y + b1);
    ((float2*)g_s)[w * 32 + l] = r;
}

// ---------------- GEMM: out[N,64] = act(A[N,K] @ W[K,64]) ----------------
template <int K, bool LEAKY, bool BNACC>
__global__ __launch_bounds__(256) void k_gemm(const float* __restrict__ A,
                                              const float* __restrict__ W,
                                              float* __restrict__ out) {
    __shared__ float Ws[K * 64];
    __shared__ float As[16 * K];
    int tid = threadIdx.x;
    for (int i = tid; i < K * 16; i += 256)
        ((float4*)Ws)[i] = ((const float4*)W)[i];
    int c = tid & 63, tg = tid >> 6;
    float bsum = 0.f, bsq = 0.f;
    for (int tile = blockIdx.x; tile < NN / 16; tile += gridDim.x) {
        __syncthreads();
        const float4* Ag = (const float4*)(A + tile * 16 * K);
        for (int i = tid; i < 4 * K; i += 256)
            ((float4*)As)[i] = Ag[i];
        __syncthreads();
        float acc0 = 0.f, acc1 = 0.f, acc2 = 0.f, acc3 = 0.f;
        const float* a0 = &As[(tg * 4 + 0) * K];
        const float* a1 = &As[(tg * 4 + 1) * K];
        const float* a2 = &As[(tg * 4 + 2) * K];
        const float* a3 = &As[(tg * 4 + 3) * K];
#pragma unroll
        for (int k = 0; k < K; k += 4) {
            float w0 = Ws[(k + 0) * 64 + c], w1 = Ws[(k + 1) * 64 + c];
            float w2 = Ws[(k + 2) * 64 + c], w3 = Ws[(k + 3) * 64 + c];
            float4 v;
            v = *(const float4*)(a0 + k); acc0 += v.x * w0 + v.y * w1 + v.z * w2 + v.w * w3;
            v = *(const float4*)(a1 + k); acc1 += v.x * w0 + v.y * w1 + v.z * w2 + v.w * w3;
            v = *(const float4*)(a2 + k); acc2 += v.x * w0 + v.y * w1 + v.z * w2 + v.w * w3;
            v = *(const float4*)(a3 + k); acc3 += v.x * w0 + v.y * w1 + v.z * w2 + v.w * w3;
        }
        int row0 = tile * 16 + tg * 4;
        float r[4] = {acc0, acc1, acc2, acc3};
#pragma unroll
        for (int j = 0; j < 4; j++) {
            float v = r[j];
            if (LEAKY) v = v > 0.f ? v : 0.01f * v;
            out[(row0 + j) * 64 + c] = v;
            if (BNACC) { bsum += v; bsq += v * v; }
        }
    }
    if (BNACC) {
        __syncthreads();
        As[tg * 64 + c] = bsum;
        As[256 + tg * 64 + c] = bsq;
        __syncthreads();
        if (tg == 0) {
            float s0 = As[c] + As[64 + c] + As[128 + c] + As[192 + c];
            float q0 = As[256 + c] + As[320 + c] + As[384 + c] + As[448 + c];
            atomicAdd(&g_colsum[c], s0);
            atomicAdd(&g_colsum[64 + c], q0);
        }
    }
}

// ---------------- BatchNorm (only the last layer's BN output is used) ----------------
__global__ void k_bn_fin() {
    int c = threadIdx.x;  // 64 threads
    float m   = g_colsum[c] * (1.0f / NN);
    float var = g_colsum[64 + c] * (1.0f / NN) - m * m;
    g_bnp[c]      = m;
    g_bnp[64 + c] = rsqrtf(var + 1e-4f);
}

__global__ void k_bn_apply(const float* __restrict__ gamma, const float* __restrict__ beta,
                           float* __restrict__ xl) {
    int i = blockIdx.x * blockDim.x + threadIdx.x;
    if (i < NN * 64) {
        int c = i & 63;
        xl[i] = gamma[c] * (g_x[i] - g_bnp[c]) * g_bnp[64 + c] + beta[c];
    }
}

// ---------------- final: g_out = concat(x_local, s) @ Wh + bh ----------------
__global__ __launch_bounds__(256) void k_final_gemm(const float* __restrict__ xl,
                                                    const float* __restrict__ W,
                                                    const float* __restrict__ bias) {
    __shared__ float Ws[128 * 64];
    __shared__ float As[16 * 128];
    int tid = threadIdx.x;
    for (int i = tid; i < 128 * 16; i += 256)
        ((float4*)Ws)[i] = ((const float4*)W)[i];
    int c = tid & 63, tg = tid >> 6;
    float bval = bias[c];
    for (int tile = blockIdx.x; tile < NN / 16; tile += gridDim.x) {
        __syncthreads();
        for (int i = tid; i < 512; i += 256) {
            int r = i >> 5, kk = i & 31;
            int row = tile * 16 + r;
            float4 v = (kk < 16) ? ((const float4*)xl)[row * 16 + kk]
                                 : ((const float4*)g_s)[row * 16 + (kk - 16)];
            ((float4*)As)[i] = v;
        }
        __syncthreads();
        float acc0 = bval, acc1 = bval, acc2 = bval, acc3 = bval;
        const float* a0 = &As[(tg * 4 + 0) * 128];
        const float* a1 = &As[(tg * 4 + 1) * 128];
        const float* a2 = &As[(tg * 4 + 2) * 128];
        const float* a3 = &As[(tg * 4 + 3) * 128];
#pragma unroll
        for (int k = 0; k < 128; k += 4) {
            float w0 = Ws[(k + 0) * 64 + c], w1 = Ws[(k + 1) * 64 + c];
            float w2 = Ws[(k + 2) * 64 + c], w3 = Ws[(k + 3) * 64 + c];
            float4 v;
            v = *(const float4*)(a0 + k); acc0 += v.x * w0 + v.y * w1 + v.z * w2 + v.w * w3;
            v = *(const float4*)(a1 + k); acc1 += v.x * w0 + v.y * w1 + v.z * w2 + v.w * w3;
            v = *(const float4*)(a2 + k); acc2 += v.x * w0 + v.y * w1 + v.z * w2 + v.w * w3;
            v = *(const float4*)(a3 + k); acc3 += v.x * w0 + v.y * w1 + v.z * w2 + v.w * w3;
        }
        int row0 = tile * 16 + tg * 4;
        g_out[(row0 + 0) * 64 + c] = acc0;
        g_out[(row0 + 1) * 64 + c] = acc1;
        g_out[(row0 + 2) * 64 + c] = acc2;
        g_out[(row0 + 3) * 64 + c] = acc3;
    }
}

// ---------------- pool: batch is SORTED -> binary-search range sum ----------------
__device__ __forceinline__ int lower_bound_i(const int* a, int key) {
    int lo = 0, hi = NN;
    while (lo < hi) {
        int mid = (lo + hi) >> 1;
        if (a[mid] < key) lo = mid + 1; else hi = mid;
    }
    return lo;
}

__global__ void k_pool(const int* __restrict__ batch, float* __restrict__ pooled,
                       long long limit) {
    int g = blockIdx.x;
    int tid = threadIdx.x;
    int c = tid & 63, p = tid >> 6;
    int lo = lower_bound_i(batch, g);
    int hi = lower_bound_i(batch, g + 1);
    float acc = 0.f;
    for (int r = lo + p; r < hi; r += 4) acc += g_out[r * 64 + c];
    __shared__ float red[256];
    red[tid] = acc;
    __syncthreads();
    if (p == 0) {
        long long oi = (long long)g * 64 + c;
        if (oi < limit)
            pooled[oi] = red[c] + red[64 + c] + red[128 + c] + red[192 + c];
    }
}

// ---------------- launch ----------------
extern "C" void kernel_launch(void* const* d_in, const int* in_sizes, int n_in,
                              void* d_out, int out_size) {
    const float *x = 0, *s = 0, *W1 = 0, *W2 = 0, *gamma = 0, *beta = 0;
    const float *Wg = 0, *bg = 0, *Wh = 0, *bh = 0;
    const int *ei = 0, *batch = 0;
    for (int i = 0; i < n_in; i++) {
        int sz = in_sizes[i];
        const void* p = d_in[i];
        switch (sz) {
            case 3200000: if (!x) x = (const float*)p; else s = (const float*)p; break;
            case 24576:   W1 = (const float*)p; break;
            case 12288:   if (!W2) W2 = (const float*)p; else Wg = (const float*)p; break;
            case 192:     if (!gamma) gamma = (const float*)p;
                          else if (!beta) beta = (const float*)p;
                          else bg = (const float*)p; break;
            case 8192:    Wh = (const float*)p; break;
            case 64:      bh = (const float*)p; break;
            case 1600000: ei = (const int*)p; break;
            case 50000:   batch = (const int*)p; break;
            default: break;
        }
    }

    const int* esrc = ei;
    const int* edst = ei + EE;

    float *p_agg, *p_tmp, *p_x, *p_s;
    cudaGetSymbolAddress((void**)&p_agg, g_agg);
    cudaGetSymbolAddress((void**)&p_tmp, g_tmp);
    cudaGetSymbolAddress((void**)&p_x,   g_x);
    cudaGetSymbolAddress((void**)&p_s,   g_s);

    long long osz = (long long)out_size;
    float* out = (float*)d_out;
    bool full = (osz >= (long long)GG * 64 + (long long)NN * 64);
    float* xl = full ? out + GG * 64 : p_agg;   // g_agg dead after layer loop

    // CSR build (per call; deterministic)
    k_zero_deg<<<(NN + 255) / 256, 256>>>();
    k_deg<<<(EE + 255) / 256, 256>>>(edst);
    k_dinv<<<(NN + 255) / 256, 256>>>();
    k_scan<<<1, 1024>>>();
    k_fill<<<(EE + 255) / 256, 256>>>(esrc, edst);

    const int GW = (NN * 32 + 255) / 256;   // warp-per-node grids
    for (int i = 0; i < 3; i++) {
        const float* xin = (i == 0) ? x : p_x;
        const float* sin = (i == 0) ? s : p_s;
        k_gin_gather<<<GW, 256>>>((const float4*)xin, (const float4*)sin);
        k_gemm<128, true, false><<<592, 256>>>(p_agg, W1 + i * 128 * 64, p_tmp);
        if (i == 2)
            k_gemm<64, false, true><<<1184, 256>>>(p_tmp, W2 + i * 64 * 64, p_x);
        else
            k_gemm<64, false, false><<<1184, 256>>>(p_tmp, W2 + i * 64 * 64, p_x);
        // GCN: sw = s @ Wg[i] -> g_tmp
        k_gemm<64, false, false><<<1184, 256>>>(sin, Wg + i * 64 * 64, p_tmp);
        k_gcn_gather<<<GW, 256>>>((const float2*)p_tmp, bg + i * 64);
    }

    k_bn_fin<<<1, 64>>>();
    k_bn_apply<<<NN * 64 / 256, 256>>>(gamma + 2 * 64, beta + 2 * 64, xl);
    k_final_gemm<<<592, 256>>>(xl, Wh, bh);
    k_pool<<<GG, 256>>>(batch, out, osz);
}